// round 11
// baseline (speedup 1.0000x reference)
#include <cuda_runtime.h>
#include <cuda_bf16.h>

// CosineLoss: result = mean_i (1 - output[i, targets[i]])
// Multi-CTA scattered gather + deterministic last-block reduction.

#define TPB 128
#define MAX_CTAS 1024

__device__ float g_partials[MAX_CTAS];
__device__ int   g_done_count = 0;

__global__ __launch_bounds__(TPB, 1)
void cosine_loss_kernel(const float* __restrict__ out,
                        const int*   __restrict__ tgt32,  // raw targets view
                        int n, int num_classes,
                        float* __restrict__ res)
{
    // int64 vs int32 target detection (little-endian): int64 class indices
    // < 32000 have zero odd words. FP probability with int32 data ~ (1/32000)^4.
    const bool is64 = ((tgt32[1] | tgt32[3] | tgt32[5] | tgt32[7]) == 0);

    const int tid = threadIdx.x;
    const int row = blockIdx.x * TPB + tid;

    float partial = 0.0f;
    if (row < n) {
        const int idx = is64 ? tgt32[2 * row] : tgt32[row];
        partial = __ldg(&out[(long long)row * num_classes + idx]);
    }

    // Warp reduce (fixed tree -> deterministic)
    #pragma unroll
    for (int off = 16; off > 0; off >>= 1)
        partial += __shfl_xor_sync(0xFFFFFFFFu, partial, off);

    __shared__ float warp_sums[TPB / 32];
    const int wid = tid >> 5;
    const int lid = tid & 31;
    if (lid == 0) warp_sums[wid] = partial;
    __syncthreads();

    __shared__ bool s_last;
    if (tid == 0) {
        float cta_sum = 0.0f;
        #pragma unroll
        for (int w = 0; w < TPB / 32; w++) cta_sum += warp_sums[w];
        g_partials[blockIdx.x] = cta_sum;
        __threadfence();                                   // publish partial
        int prev = atomicAdd(&g_done_count, 1);
        s_last = (prev == (int)gridDim.x - 1);
    }
    __syncthreads();

    // Last-arriving CTA reduces all partials in a FIXED order (deterministic).
    if (s_last) {
        const int nblocks = (int)gridDim.x;
        float s = 0.0f;
        for (int i = tid; i < nblocks; i += TPB)
            s += g_partials[i];                            // fixed assignment
        #pragma unroll
        for (int off = 16; off > 0; off >>= 1)
            s += __shfl_xor_sync(0xFFFFFFFFu, s, off);

        __shared__ float fin[TPB / 32];
        if (lid == 0) fin[wid] = s;
        __syncthreads();
        if (tid == 0) {
            float total = 0.0f;
            #pragma unroll
            for (int w = 0; w < TPB / 32; w++) total += fin[w];
            res[0] = 1.0f - total / (float)n;
            g_done_count = 0;                              // reset for next replay
            __threadfence();
        }
    }
}

extern "C" void kernel_launch(void* const* d_in, const int* in_sizes, int n_in,
                              void* d_out, int out_size)
{
    const float* output = (const float*)d_in[0];
    const int*   tgtraw = (const int*)d_in[1];
    float*       res    = (float*)d_out;

    const int n = in_sizes[1];                   // 8192
    const int num_classes = in_sizes[0] / n;     // 32000

    int nblocks = (n + TPB - 1) / TPB;           // 64 for n=8192
    if (nblocks > MAX_CTAS) nblocks = MAX_CTAS;  // safety (n <= 131072 covered)

    cosine_loss_kernel<<<nblocks, TPB>>>(output, tgtraw, n, num_classes, res);
}

// round 12
// speedup vs baseline: 1.2977x; 1.2977x over previous
#include <cuda_runtime.h>
#include <cuda_bf16.h>

// CosineLoss: result = mean_i (1 - output[i, targets[i]])
// Multi-CTA scattered gather; cross-CTA reduction via ONE packed u64 atomic
// per CTA (fixed-point sum in low 56 bits + arrival count in high 8 bits).
// Integer adds are commutative -> deterministic for any arrival order.

#define TPB 128

__device__ unsigned long long g_acc = 0ull;   // [63:56]=count, [55:0]=sum+offsets

// fixed-point: value * 2^30, biased by OFFSET so every contribution is positive
#define FP_SCALE   1073741824.0f              // 2^30
#define FP_OFFSET  (1ll << 45)
#define CNT_ONE    (1ull << 56)
#define LOW_MASK   ((1ull << 56) - 1ull)

__global__ __launch_bounds__(TPB, 1)
void cosine_loss_kernel(const float* __restrict__ out,
                        const int*   __restrict__ tgt32,  // raw targets view
                        int n, int num_classes,
                        float* __restrict__ res)
{
    const int tid = threadIdx.x;
    const int row = blockIdx.x * TPB + tid;

    // Issue detection words AND both index hypotheses in parallel (no serial
    // detect->load dependency). Detection: little-endian int64 class indices
    // < 32000 have zero odd words; FP probability with int32 data ~(1/32000)^4.
    const int d1 = __ldg(&tgt32[1]);
    const int d3 = __ldg(&tgt32[3]);
    const int d5 = __ldg(&tgt32[5]);
    const int d7 = __ldg(&tgt32[7]);
    int i64 = 0, i32 = 0;
    if (row < n) {
        i64 = __ldg(&tgt32[2 * row]);   // int64 hypothesis (low word)
        i32 = __ldg(&tgt32[row]);       // int32 hypothesis
    }
    const bool is64 = ((d1 | d3 | d5 | d7) == 0);
    const int idx = is64 ? i64 : i32;

    float partial = 0.0f;
    if (row < n)
        partial = __ldg(&out[(long long)row * num_classes + idx]);

    // Warp reduce (fixed tree)
    #pragma unroll
    for (int off = 16; off > 0; off >>= 1)
        partial += __shfl_xor_sync(0xFFFFFFFFu, partial, off);

    __shared__ float warp_sums[TPB / 32];
    const int wid = tid >> 5;
    const int lid = tid & 31;
    if (lid == 0) warp_sums[wid] = partial;
    __syncthreads();

    if (tid == 0) {
        float cta_sum = 0.0f;
        #pragma unroll
        for (int w = 0; w < TPB / 32; w++) cta_sum += warp_sums[w];

        // Pack: one atomic carries both the fixed-point sum and the arrival.
        long long fx = llrintf(cta_sum * FP_SCALE);        // |cta_sum| << 2^15
        unsigned long long pack = CNT_ONE + (unsigned long long)(fx + FP_OFFSET);
        unsigned long long prev = atomicAdd(&g_acc, pack);

        if ((prev >> 56) == (unsigned long long)(gridDim.x - 1)) {
            // Last arriver: full sum is prev + our pack (no extra global read).
            unsigned long long full = prev + pack;
            long long sum_fx = (long long)(full & LOW_MASK)
                             - (long long)gridDim.x * FP_OFFSET;
            double total = (double)sum_fx * (1.0 / (double)FP_SCALE);
            res[0] = (float)(1.0 - total / (double)n);
            g_acc = 0ull;                                  // reset for next replay
            __threadfence();
        }
    }
}

extern "C" void kernel_launch(void* const* d_in, const int* in_sizes, int n_in,
                              void* d_out, int out_size)
{
    const float* output = (const float*)d_in[0];
    const int*   tgtraw = (const int*)d_in[1];
    float*       res    = (float*)d_out;

    const int n = in_sizes[1];                   // 8192
    const int num_classes = in_sizes[0] / n;     // 32000

    const int nblocks = (n + TPB - 1) / TPB;     // 64

    cosine_loss_kernel<<<nblocks, TPB>>>(output, tgtraw, n, num_classes, res);
}

// round 13
// speedup vs baseline: 1.3413x; 1.0337x over previous
#include <cuda_runtime.h>
#include <cuda_bf16.h>

// CosineLoss: result = mean_i (1 - output[i, targets[i]])
// 64 CTAs x 128 threads, 1 gather/thread. Reduction: per-thread fixed-point
// (x 2^20) -> warp REDUX.SUM -> ONE packed u64 global atomic per warp
// ([63:42]=arrival count, [41:0]=biased fixed-point sum). Integer adds are
// commutative -> bitwise deterministic for any arrival order. The warp whose
// atomic return shows all arrivals computes and stores the final mean.

#define TPB 128

__device__ unsigned long long g_acc = 0ull;

#define FXS      1048576.0f            // 2^20 quantization scale
#define OFFS     (1ll << 30)           // bias so each warp contribution > 0
#define CNT_ONE  (1ull << 42)
#define LOW_MASK ((1ull << 42) - 1ull)

__global__ __launch_bounds__(TPB, 1)
void cosine_loss_kernel(const float* __restrict__ out,
                        const int*   __restrict__ tgt32,  // raw targets view
                        int n, int num_classes,
                        float* __restrict__ res)
{
    const int tid = threadIdx.x;
    const int row = blockIdx.x * TPB + tid;
    const int lid = tid & 31;

    // Width detection (int64 targets have zero odd words for class ids
    // < 32000; FP prob with int32 data ~(1/32000)^4) issued in PARALLEL with
    // both index hypotheses -> no serial detect->load dependency.
    const int4 w0 = __ldg((const int4*)&tgt32[0]);
    const int4 w1 = __ldg((const int4*)&tgt32[4]);
    int i64 = 0, i32 = 0;
    if (row < n) {
        i64 = __ldg(&tgt32[2 * row]);   // int64 hypothesis (low word)
        i32 = __ldg(&tgt32[row]);       // int32 hypothesis
    }
    const bool is64 = ((w0.y | w0.w | w1.y | w1.w) == 0);
    const int idx = is64 ? i64 : i32;

    float v = 0.0f;
    if (row < n)
        v = __ldg(&out[(long long)row * num_classes + idx]);

    // Quantize, then single-instruction integer warp reduction (deterministic).
    const int fx = __float2int_rn(v * FXS);            // |fx| << 2^24
    const int warp_fx = __reduce_add_sync(0xFFFFFFFFu, fx);   // |.| < 2^29

    if (lid == 0) {
        const unsigned long long pack =
            CNT_ONE + (unsigned long long)((long long)warp_fx + OFFS);
        const unsigned long long prev = atomicAdd(&g_acc, pack);

        const unsigned int nw_total = gridDim.x * (TPB / 32);
        if ((unsigned int)(prev >> 42) == nw_total - 1u) {
            // Last arriver: full sum available from the atomic's return.
            const unsigned long long full = prev + pack;
            const long long sum_fx = (long long)(full & LOW_MASK)
                                   - (long long)nw_total * OFFS;
            const double total = (double)sum_fx * (1.0 / (double)(1 << 20));
            res[0] = (float)(1.0 - total / (double)n);
            g_acc = 0ull;   // same-thread same-address: ordered after atomic;
                            // drained at kernel end -> visible to next replay
        }
    }
}

extern "C" void kernel_launch(void* const* d_in, const int* in_sizes, int n_in,
                              void* d_out, int out_size)
{
    const float* output = (const float*)d_in[0];
    const int*   tgtraw = (const int*)d_in[1];
    float*       res    = (float*)d_out;

    const int n = in_sizes[1];                   // 8192
    const int num_classes = in_sizes[0] / n;     // 32000

    const int nblocks = (n + TPB - 1) / TPB;     // 64

    cosine_loss_kernel<<<nblocks, TPB>>>(output, tgtraw, n, num_classes, res);
}